// round 1
// baseline (speedup 1.0000x reference)
#include <cuda_runtime.h>
#include <math.h>

// Problem constants
#define NB 16
#define NQ 1024
#define NKK 1024
#define DM 512
#define NH 8
#define DKH 64
#define NM 40
#define NKP 1088          // padded key length: 17 * 64
#define ROWS (NB*NQ)      // 16384

// -------- scratch (static device memory: allowed) --------
__device__ float g_Q[(size_t)NB*NH*NQ*DKH];     // [bh][1024][64]
__device__ float g_K[(size_t)NB*NH*NKP*DKH];    // [bh][1088][64]
__device__ float g_V[(size_t)NB*NH*NKP*DKH];    // [bh][1088][64]
__device__ float g_O[(size_t)ROWS*DM];          // attention out, [row][512]
__device__ float g_X[(size_t)ROWS*DM];          // proj + residual, [row][512]

// ============================================================
// Memory-slot fill: rows 1024..1087 of g_K/g_V (scaled mem, zero pad)
// ============================================================
__global__ void memfill_kernel(const float* __restrict__ memK,
                               const float* __restrict__ memV)
{
    const int bh = blockIdx.x;          // 0..127
    const int h = bh & 7;
    const float sk = 8.0f;              // sqrt(64)
    const float sv = 6.3245553203367587f; // sqrt(40)
    for (int idx = threadIdx.x; idx < 64*64; idx += blockDim.x) {
        const int m = idx >> 6;
        const int d = idx & 63;
        float kv = 0.f, vv = 0.f;
        if (m < NM) {
            kv = sk * memK[m*DM + h*DKH + d];
            vv = sv * memV[m*DM + h*DKH + d];
        }
        const size_t o = ((size_t)bh*NKP + 1024 + m)*DKH + d;
        g_K[o] = kv;
        g_V[o] = vv;
    }
}

// ============================================================
// Tiled SGEMM: C[16384,512] = A[16384,512] @ W[512,512] + bias
// BM=BN=128, BK=8, 256 threads, TM=TN=8
// MODE 0: scatter -> g_Q   MODE 1: scatter -> g_K rows 0..1023
// MODE 2: scatter -> g_V   MODE 3: A=g_O, += resid, -> g_X
// ============================================================
template<int MODE>
__global__ void __launch_bounds__(256) gemm_kernel(const float* __restrict__ A,
                                                   const float* __restrict__ W,
                                                   const float* __restrict__ bias,
                                                   const float* __restrict__ resid)
{
    __shared__ float As[8][128];   // transposed A tile [k][m]
    __shared__ float Bs[8][128];   // [k][n]

    const int tid = threadIdx.x;
    const int bm = blockIdx.y, bn = blockIdx.x;
    const int arow = tid >> 1, acol = (tid & 1) << 2;
    const int brow = tid >> 5, bcol = (tid & 31) << 2;
    const int tmg = (tid >> 4) << 3, tng = (tid & 15) << 3;

    const float* Ap = (MODE == 3) ? (const float*)g_O : A;
    const float* Abase = Ap + ((size_t)(bm*128 + arow))*DM + acol;
    const float* Wbase = W + (size_t)brow*DM + bn*128 + bcol;

    float acc[8][8];
#pragma unroll
    for (int i = 0; i < 8; i++)
#pragma unroll
        for (int j = 0; j < 8; j++) acc[i][j] = 0.f;

    for (int kb = 0; kb < DM; kb += 8) {
        const float4 a4 = *(const float4*)(Abase + kb);
        const float4 b4 = *(const float4*)(Wbase + (size_t)kb*DM);
        __syncthreads();
        As[acol+0][arow] = a4.x;
        As[acol+1][arow] = a4.y;
        As[acol+2][arow] = a4.z;
        As[acol+3][arow] = a4.w;
        *(float4*)(&Bs[brow][bcol]) = b4;
        __syncthreads();
#pragma unroll
        for (int k = 0; k < 8; k++) {
            float rm[8], rn[8];
            *(float4*)(rm)   = *(const float4*)(&As[k][tmg]);
            *(float4*)(rm+4) = *(const float4*)(&As[k][tmg+4]);
            *(float4*)(rn)   = *(const float4*)(&Bs[k][tng]);
            *(float4*)(rn+4) = *(const float4*)(&Bs[k][tng+4]);
#pragma unroll
            for (int i = 0; i < 8; i++)
#pragma unroll
                for (int j = 0; j < 8; j++)
                    acc[i][j] += rm[i]*rn[j];
        }
    }

#pragma unroll
    for (int i = 0; i < 8; i++) {
        const int r = bm*128 + tmg + i;
        const int bb = r >> 10, n = r & 1023;
#pragma unroll
        for (int jj = 0; jj < 8; jj += 4) {
            const int c = bn*128 + tng + jj;
            float4 v;
            v.x = acc[i][jj+0] + bias[c+0];
            v.y = acc[i][jj+1] + bias[c+1];
            v.z = acc[i][jj+2] + bias[c+2];
            v.w = acc[i][jj+3] + bias[c+3];
            if (MODE == 3) {
                const float4 rv = *(const float4*)(resid + (size_t)r*DM + c);
                v.x += rv.x; v.y += rv.y; v.z += rv.z; v.w += rv.w;
                *(float4*)(&g_X[(size_t)r*DM + c]) = v;
            } else {
                const int h = c >> 6, d = c & 63;
                if (MODE == 0)
                    *(float4*)(&g_Q[(((size_t)bb*NH + h)*NQ + n)*DKH + d]) = v;
                else if (MODE == 1)
                    *(float4*)(&g_K[(((size_t)bb*NH + h)*NKP + n)*DKH + d]) = v;
                else
                    *(float4*)(&g_V[(((size_t)bb*NH + h)*NKP + n)*DKH + d]) = v;
            }
        }
    }
}

// ============================================================
// Flash attention: per block = one (b,h) and 64 queries.
// 17 key-tiles of 64. Weighted logits for k<1024, mask k>=1064.
// 256 threads, 4x4 register tile per thread.
// ============================================================
#define ATT_SMEM_BYTES ((64*68 + 64*65 + 64*68 + 64*68) * 4)

__global__ void __launch_bounds__(256) attn_kernel(const float* __restrict__ AW)
{
    extern __shared__ float sm[];
    float* QT = sm;                 // [64 d][68]  (d-major, transposed Q)
    float* KS = QT + 64*68;         // [64 k][65]  (k-major, natural)
    float* VS = KS + 64*65;         // [64 k][68]
    float* PS = VS + 64*68;         // [64 q][68]

    const int tid = threadIdx.x;
    const int bh = blockIdx.y;
    const int b = bh >> 3;
    const int h = bh & 7;
    const int q0 = blockIdx.x << 6;
    const int tm0 = (tid >> 4) << 2;   // query sub-tile
    const int tn0 = (tid & 15) << 2;   // key / dv sub-tile

    // load Q tile transposed (once per block)
    {
        const int r = tid >> 2;
        const int cb = (tid & 3) << 4;
        const float* qp = g_Q + ((size_t)bh*NQ + q0 + r)*DKH + cb;
#pragma unroll
        for (int u = 0; u < 4; u++) {
            const float4 t = *(const float4*)(qp + 4*u);
            const int c = cb + 4*u;
            QT[(c+0)*68 + r] = t.x;
            QT[(c+1)*68 + r] = t.y;
            QT[(c+2)*68 + r] = t.z;
            QT[(c+3)*68 + r] = t.w;
        }
    }

    float o[4][4];
    float mrow[4], lrow[4];
#pragma unroll
    for (int i = 0; i < 4; i++) {
        mrow[i] = -1e30f; lrow[i] = 0.f;
#pragma unroll
        for (int j = 0; j < 4; j++) o[i][j] = 0.f;
    }

    for (int kt = 0; kt < 17; kt++) {
        __syncthreads();
        // load K (natural, scalar stores into 65-stride) / V (float4 into 68-stride)
        {
            const int r = tid >> 2;
            const int cb = (tid & 3) << 4;
            const float* kp = g_K + ((size_t)bh*NKP + kt*64 + r)*DKH + cb;
            const float* vp = g_V + ((size_t)bh*NKP + kt*64 + r)*DKH + cb;
#pragma unroll
            for (int u = 0; u < 4; u++) {
                const float4 t = *(const float4*)(kp + 4*u);
                const int c = cb + 4*u;
                KS[r*65 + c+0] = t.x;
                KS[r*65 + c+1] = t.y;
                KS[r*65 + c+2] = t.z;
                KS[r*65 + c+3] = t.w;
                const float4 tv = *(const float4*)(vp + 4*u);
                *(float4*)(&VS[r*68 + c]) = tv;
            }
        }
        __syncthreads();

        // scores S = Q K^T  (register-tiled)
        float sc[4][4];
#pragma unroll
        for (int i = 0; i < 4; i++)
#pragma unroll
            for (int j = 0; j < 4; j++) sc[i][j] = 0.f;

#pragma unroll 8
        for (int d = 0; d < 64; d++) {
            float qv[4];
            *(float4*)qv = *(const float4*)(QT + d*68 + tm0);
            float kv[4];
            kv[0] = KS[(tn0+0)*65 + d];
            kv[1] = KS[(tn0+1)*65 + d];
            kv[2] = KS[(tn0+2)*65 + d];
            kv[3] = KS[(tn0+3)*65 + d];
#pragma unroll
            for (int i = 0; i < 4; i++)
#pragma unroll
                for (int j = 0; j < 4; j++)
                    sc[i][j] += qv[i]*kv[j];
        }

        // scale by 1/sqrt(dk), apply attention_weights (k<1024), mask pad
        if (kt < 16) {
#pragma unroll
            for (int i = 0; i < 4; i++) {
                const float4 w4 = *(const float4*)(AW +
                    ((size_t)b*NQ + q0 + tm0 + i)*NKK + kt*64 + tn0);
                sc[i][0] = sc[i][0]*0.125f*w4.x;
                sc[i][1] = sc[i][1]*0.125f*w4.y;
                sc[i][2] = sc[i][2]*0.125f*w4.z;
                sc[i][3] = sc[i][3]*0.125f*w4.w;
            }
        } else {
#pragma unroll
            for (int i = 0; i < 4; i++)
#pragma unroll
                for (int j = 0; j < 4; j++)
                    sc[i][j] = (tn0 + j < NM) ? sc[i][j]*0.125f : -1e30f;
        }

        // online softmax (reduce over 16-lane row groups)
#pragma unroll
        for (int i = 0; i < 4; i++) {
            float rm = fmaxf(fmaxf(sc[i][0], sc[i][1]), fmaxf(sc[i][2], sc[i][3]));
            rm = fmaxf(rm, __shfl_xor_sync(0xffffffffu, rm, 1));
            rm = fmaxf(rm, __shfl_xor_sync(0xffffffffu, rm, 2));
            rm = fmaxf(rm, __shfl_xor_sync(0xffffffffu, rm, 4));
            rm = fmaxf(rm, __shfl_xor_sync(0xffffffffu, rm, 8));
            const float mnew = fmaxf(mrow[i], rm);
            const float corr = __expf(mrow[i] - mnew);
            mrow[i] = mnew;
            const float p0 = __expf(sc[i][0] - mnew);
            const float p1 = __expf(sc[i][1] - mnew);
            const float p2 = __expf(sc[i][2] - mnew);
            const float p3 = __expf(sc[i][3] - mnew);
            float ps = p0 + p1 + p2 + p3;
            ps += __shfl_xor_sync(0xffffffffu, ps, 1);
            ps += __shfl_xor_sync(0xffffffffu, ps, 2);
            ps += __shfl_xor_sync(0xffffffffu, ps, 4);
            ps += __shfl_xor_sync(0xffffffffu, ps, 8);
            lrow[i] = lrow[i]*corr + ps;
            o[i][0] *= corr; o[i][1] *= corr; o[i][2] *= corr; o[i][3] *= corr;
            *(float4*)(&PS[(tm0+i)*68 + tn0]) = make_float4(p0, p1, p2, p3);
        }
        __syncthreads();

        // O += P @ V  (register-tiled)
#pragma unroll 8
        for (int k = 0; k < 64; k++) {
            float vv[4];
            *(float4*)vv = *(const float4*)(&VS[k*68 + tn0]);
            const float p0 = PS[(tm0+0)*68 + k];
            const float p1 = PS[(tm0+1)*68 + k];
            const float p2 = PS[(tm0+2)*68 + k];
            const float p3 = PS[(tm0+3)*68 + k];
#pragma unroll
            for (int j = 0; j < 4; j++) {
                o[0][j] += p0*vv[j];
                o[1][j] += p1*vv[j];
                o[2][j] += p2*vv[j];
                o[3][j] += p3*vv[j];
            }
        }
    }

    // normalize and write [b, q, h*64 + dv]
#pragma unroll
    for (int i = 0; i < 4; i++) {
        const float inv = 1.0f / lrow[i];
        float4 r;
        r.x = o[i][0]*inv; r.y = o[i][1]*inv; r.z = o[i][2]*inv; r.w = o[i][3]*inv;
        *(float4*)(&g_O[((size_t)b*NQ + q0 + tm0 + i)*DM + h*DKH + tn0]) = r;
    }
}

// ============================================================
// LayerNorm: warp per row (512 elems), eps=1e-3
// ============================================================
__global__ void __launch_bounds__(256) ln_kernel(const float* __restrict__ gamma,
                                                 const float* __restrict__ beta,
                                                 float* __restrict__ out)
{
    const int row = blockIdx.x*8 + (threadIdx.x >> 5);
    const int lane = threadIdx.x & 31;
    const float* xr = g_X + (size_t)row*DM;
    float v[16];
    float s = 0.f, s2 = 0.f;
#pragma unroll
    for (int u = 0; u < 4; u++) {
        const float4 t = *(const float4*)(xr + lane*4 + u*128);
        v[4*u+0] = t.x; v[4*u+1] = t.y; v[4*u+2] = t.z; v[4*u+3] = t.w;
        s  += t.x + t.y + t.z + t.w;
        s2 += t.x*t.x + t.y*t.y + t.z*t.z + t.w*t.w;
    }
#pragma unroll
    for (int off = 16; off > 0; off >>= 1) {
        s  += __shfl_xor_sync(0xffffffffu, s,  off);
        s2 += __shfl_xor_sync(0xffffffffu, s2, off);
    }
    const float mu  = s * (1.f/512.f);
    const float var = s2 * (1.f/512.f) - mu*mu;
    const float rs  = rsqrtf(var + 1e-3f);
    float* orow = out + (size_t)row*DM;
#pragma unroll
    for (int u = 0; u < 4; u++) {
        const int d = lane*4 + u*128;
        const float4 g  = *(const float4*)(gamma + d);
        const float4 bt = *(const float4*)(beta + d);
        float4 r;
        r.x = g.x*(v[4*u+0]-mu)*rs + bt.x;
        r.y = g.y*(v[4*u+1]-mu)*rs + bt.y;
        r.z = g.z*(v[4*u+2]-mu)*rs + bt.z;
        r.w = g.w*(v[4*u+3]-mu)*rs + bt.w;
        *(float4*)(orow + d) = r;
    }
}

// ============================================================
extern "C" void kernel_launch(void* const* d_in, const int* in_sizes, int n_in,
                              void* d_out, int out_size)
{
    (void)in_sizes; (void)n_in; (void)out_size;
    const float* queries = (const float*)d_in[0];
    const float* keys    = (const float*)d_in[1];
    const float* values  = (const float*)d_in[2];
    const float* aw      = (const float*)d_in[3];
    const float* Wq = (const float*)d_in[4];
    const float* bq = (const float*)d_in[5];
    const float* Wk = (const float*)d_in[6];
    const float* bk = (const float*)d_in[7];
    const float* Wv = (const float*)d_in[8];
    const float* bv = (const float*)d_in[9];
    const float* Wo = (const float*)d_in[10];
    const float* bo = (const float*)d_in[11];
    const float* memK = (const float*)d_in[12];
    const float* memV = (const float*)d_in[13];
    const float* gamma = (const float*)d_in[14];
    const float* beta  = (const float*)d_in[15];
    float* out = (float*)d_out;

    cudaFuncSetAttribute(attn_kernel,
                         cudaFuncAttributeMaxDynamicSharedMemorySize,
                         ATT_SMEM_BYTES);

    const dim3 gg(4, 128);     // N tiles x M tiles
    memfill_kernel<<<128, 256>>>(memK, memV);
    gemm_kernel<0><<<gg, 256>>>(queries, Wq, bq, nullptr);
    gemm_kernel<1><<<gg, 256>>>(keys,    Wk, bk, nullptr);
    gemm_kernel<2><<<gg, 256>>>(values,  Wv, bv, nullptr);
    attn_kernel<<<dim3(16, 128), 256, ATT_SMEM_BYTES>>>(aw);
    gemm_kernel<3><<<gg, 256>>>(nullptr, Wo, bo, queries);
    ln_kernel<<<ROWS/8, 256>>>(gamma, beta, out);
}

// round 3
// speedup vs baseline: 1.3838x; 1.3838x over previous
#include <cuda_runtime.h>
#include <cstdint>
#include <math.h>

// Problem constants
#define NB 16
#define NQ 1024
#define NKK 1024
#define DM 512
#define NH 8
#define DKH 64
#define NM 40
#define NKP 1088          // padded key length: 17 * 64
#define ROWS (NB*NQ)      // 16384

// -------- scratch (static device memory: allowed) --------
__device__ float g_Q[(size_t)NB*NH*NQ*DKH];     // [bh][1024][64]
__device__ float g_K[(size_t)NB*NH*NKP*DKH];    // [bh][1088][64]
__device__ float g_V[(size_t)NB*NH*NKP*DKH];    // [bh][1088][64]
__device__ float g_O[(size_t)ROWS*DM];          // attention out, [row][512]
__device__ float g_X[(size_t)ROWS*DM];          // proj + residual, [row][512]
__device__ float g_Wt[4][(size_t)DM*DM];        // transposed weights [n][k]

// ============================================================
// tf32 helpers (base-ISA only: mma.sync, no tcgen05)
// ============================================================
__device__ __forceinline__ uint32_t f2tf32(float f) {
    uint32_t r;
    asm("cvt.rna.tf32.f32 %0, %1;" : "=r"(r) : "f"(f));
    return r;
}

__device__ __forceinline__ void mma_tf32(float* c, const uint32_t* a, const uint32_t* b) {
    asm volatile(
        "mma.sync.aligned.m16n8k8.row.col.f32.tf32.tf32.f32 "
        "{%0,%1,%2,%3}, {%4,%5,%6,%7}, {%8,%9}, {%0,%1,%2,%3};"
        : "+f"(c[0]), "+f"(c[1]), "+f"(c[2]), "+f"(c[3])
        : "r"(a[0]), "r"(a[1]), "r"(a[2]), "r"(a[3]), "r"(b[0]), "r"(b[1]));
}

// ============================================================
// Weight transpose: g_Wt[z][n][k] = W_z[k][n]  (512x512 each)
// ============================================================
__global__ void wt_kernel(const float* __restrict__ Wq, const float* __restrict__ Wk,
                          const float* __restrict__ Wv, const float* __restrict__ Wo)
{
    __shared__ float t[32][33];
    const int z = blockIdx.z;
    const float* W = (z == 0) ? Wq : (z == 1) ? Wk : (z == 2) ? Wv : Wo;
    const int tx = threadIdx.x, ty = threadIdx.y;
    const int nx = blockIdx.x*32 + tx;
    const int ky = blockIdx.y*32 + ty;
#pragma unroll
    for (int i = 0; i < 32; i += 8)
        t[ty + i][tx] = W[(size_t)(ky + i)*DM + nx];
    __syncthreads();
    const int ok = blockIdx.y*32 + tx;
    const int on = blockIdx.x*32 + ty;
#pragma unroll
    for (int i = 0; i < 32; i += 8)
        g_Wt[z][(size_t)(on + i)*DM + ok] = t[tx][ty + i];
}

// ============================================================
// Memory-slot fill: rows 1024..1087 of g_K/g_V (scaled mem, zero pad)
// ============================================================
__global__ void memfill_kernel(const float* __restrict__ memK,
                               const float* __restrict__ memV)
{
    const int bh = blockIdx.x;          // 0..127
    const int h = bh & 7;
    const float sk = 8.0f;              // sqrt(64)
    const float sv = 6.3245553203367587f; // sqrt(40)
    for (int idx = threadIdx.x; idx < 64*64; idx += blockDim.x) {
        const int m = idx >> 6;
        const int d = idx & 63;
        float kv = 0.f, vv = 0.f;
        if (m < NM) {
            kv = sk * memK[m*DM + h*DKH + d];
            vv = sv * memV[m*DM + h*DKH + d];
        }
        const size_t o = ((size_t)bh*NKP + 1024 + m)*DKH + d;
        g_K[o] = kv;
        g_V[o] = vv;
    }
}

// ============================================================
// mma.sync tf32 GEMM: C[16384,512] = A @ Wt^T + bias
// Block 128x128, BK=32, 256 threads (8 warps, warp tile 64x32).
// MODE 0: ->g_Q  1: ->g_K  2: ->g_V  3: A=g_O, +resid -> g_X
// ============================================================
#define KPAD 36

template<int MODE>
__global__ void __launch_bounds__(256) gemm_mma(const float* __restrict__ A,
                                                int widx,
                                                const float* __restrict__ bias,
                                                const float* __restrict__ resid)
{
    __shared__ float As[128*KPAD];
    __shared__ float Bs[128*KPAD];

    const int tid = threadIdx.x;
    const int lane = tid & 31, wid = tid >> 5;
    const int wm = (wid & 1) << 6;      // warp m offset (0/64)
    const int wn = (wid >> 1) << 5;     // warp n offset (0/32/64/96)
    const int gr = lane >> 2, tc = lane & 3;
    const int m0 = blockIdx.y << 7, n0 = blockIdx.x << 7;

    const float* Ap = (MODE == 3) ? (const float*)g_O : A;
    const float* Wt = g_Wt[widx];

    const int lrow = tid >> 1;           // 0..127
    const int lcol = (tid & 1) << 4;     // 0 or 16

    const float* Ag = Ap + (size_t)(m0 + lrow)*DM + lcol;
    const float* Bg = Wt + (size_t)(n0 + lrow)*DM + lcol;
    float* as_st = &As[lrow*KPAD + lcol];
    float* bs_st = &Bs[lrow*KPAD + lcol];

    float acc[4][4][4];
#pragma unroll
    for (int i = 0; i < 4; i++)
#pragma unroll
        for (int j = 0; j < 4; j++)
#pragma unroll
            for (int r = 0; r < 4; r++) acc[i][j][r] = 0.f;

    const uint32_t* Asu = (const uint32_t*)As;
    const uint32_t* Bsu = (const uint32_t*)Bs;

    for (int kb = 0; kb < DM; kb += 32) {
        float4 av[4], bv[4];
#pragma unroll
        for (int u = 0; u < 4; u++) {
            av[u] = *(const float4*)(Ag + kb + 4*u);
            bv[u] = *(const float4*)(Bg + kb + 4*u);
        }
        __syncthreads();
#pragma unroll
        for (int u = 0; u < 4; u++) {
            uint32_t* d = (uint32_t*)(as_st + 4*u);
            d[0] = f2tf32(av[u].x); d[1] = f2tf32(av[u].y);
            d[2] = f2tf32(av[u].z); d[3] = f2tf32(av[u].w);
            uint32_t* e = (uint32_t*)(bs_st + 4*u);
            e[0] = f2tf32(bv[u].x); e[1] = f2tf32(bv[u].y);
            e[2] = f2tf32(bv[u].z); e[3] = f2tf32(bv[u].w);
        }
        __syncthreads();

#pragma unroll
        for (int ks = 0; ks < 32; ks += 8) {
            uint32_t a[4][4], b[4][2];
#pragma unroll
            for (int i = 0; i < 4; i++) {
                const int r0 = (wm + i*16 + gr)*KPAD + ks + tc;
                a[i][0] = Asu[r0];
                a[i][1] = Asu[r0 + 8*KPAD];
                a[i][2] = Asu[r0 + 4];
                a[i][3] = Asu[r0 + 8*KPAD + 4];
            }
#pragma unroll
            for (int j = 0; j < 4; j++) {
                const int r0 = (wn + j*8 + gr)*KPAD + ks + tc;
                b[j][0] = Bsu[r0];
                b[j][1] = Bsu[r0 + 4];
            }
#pragma unroll
            for (int i = 0; i < 4; i++)
#pragma unroll
                for (int j = 0; j < 4; j++)
                    mma_tf32(acc[i][j], a[i], b[j]);
        }
    }

    // epilogue: each (i,j) tile -> two float2 rows per thread
#pragma unroll
    for (int i = 0; i < 4; i++) {
        const int mA = m0 + wm + i*16 + gr;
        const int mB = mA + 8;
#pragma unroll
        for (int j = 0; j < 4; j++) {
            const int n = n0 + wn + j*8 + 2*tc;
            const float b0 = bias[n], b1 = bias[n+1];
            float2 vA = make_float2(acc[i][j][0] + b0, acc[i][j][1] + b1);
            float2 vB = make_float2(acc[i][j][2] + b0, acc[i][j][3] + b1);
            if (MODE == 3) {
                const float2 rA = *(const float2*)(resid + (size_t)mA*DM + n);
                const float2 rB = *(const float2*)(resid + (size_t)mB*DM + n);
                vA.x += rA.x; vA.y += rA.y;
                vB.x += rB.x; vB.y += rB.y;
                *(float2*)(&g_X[(size_t)mA*DM + n]) = vA;
                *(float2*)(&g_X[(size_t)mB*DM + n]) = vB;
            } else {
                const int h = n >> 6, d = n & 63;
                const int bbA = mA >> 10, nnA = mA & 1023;
                const int bbB = mB >> 10, nnB = mB & 1023;
                if (MODE == 0) {
                    *(float2*)(&g_Q[(((size_t)bbA*NH + h)*NQ + nnA)*DKH + d]) = vA;
                    *(float2*)(&g_Q[(((size_t)bbB*NH + h)*NQ + nnB)*DKH + d]) = vB;
                } else if (MODE == 1) {
                    *(float2*)(&g_K[(((size_t)bbA*NH + h)*NKP + nnA)*DKH + d]) = vA;
                    *(float2*)(&g_K[(((size_t)bbB*NH + h)*NKP + nnB)*DKH + d]) = vB;
                } else {
                    *(float2*)(&g_V[(((size_t)bbA*NH + h)*NKP + nnA)*DKH + d]) = vA;
                    *(float2*)(&g_V[(((size_t)bbB*NH + h)*NKP + nnB)*DKH + d]) = vB;
                }
            }
        }
    }
}

// ============================================================
// Flash attention: per block = one (b,h) and 64 queries. (SIMT)
// ============================================================
#define ATT_SMEM_BYTES ((64*68 + 64*65 + 64*68 + 64*68) * 4)

__global__ void __launch_bounds__(256) attn_kernel(const float* __restrict__ AW)
{
    extern __shared__ float sm[];
    float* QT = sm;                 // [64 d][68]
    float* KS = QT + 64*68;         // [64 k][65]
    float* VS = KS + 64*65;         // [64 k][68]
    float* PS = VS + 64*68;         // [64 q][68]

    const int tid = threadIdx.x;
    const int bh = blockIdx.y;
    const int b = bh >> 3;
    const int h = bh & 7;
    const int q0 = blockIdx.x << 6;
    const int tm0 = (tid >> 4) << 2;
    const int tn0 = (tid & 15) << 2;

    {
        const int r = tid >> 2;
        const int cb = (tid & 3) << 4;
        const float* qp = g_Q + ((size_t)bh*NQ + q0 + r)*DKH + cb;
#pragma unroll
        for (int u = 0; u < 4; u++) {
            const float4 t = *(const float4*)(qp + 4*u);
            const int c = cb + 4*u;
            QT[(c+0)*68 + r] = t.x;
            QT[(c+1)*68 + r] = t.y;
            QT[(c+2)*68 + r] = t.z;
            QT[(c+3)*68 + r] = t.w;
        }
    }

    float o[4][4];
    float mrow[4], lrow[4];
#pragma unroll
    for (int i = 0; i < 4; i++) {
        mrow[i] = -1e30f; lrow[i] = 0.f;
#pragma unroll
        for (int j = 0; j < 4; j++) o[i][j] = 0.f;
    }

    for (int kt = 0; kt < 17; kt++) {
        __syncthreads();
        {
            const int r = tid >> 2;
            const int cb = (tid & 3) << 4;
            const float* kp = g_K + ((size_t)bh*NKP + kt*64 + r)*DKH + cb;
            const float* vp = g_V + ((size_t)bh*NKP + kt*64 + r)*DKH + cb;
#pragma unroll
            for (int u = 0; u < 4; u++) {
                const float4 t = *(const float4*)(kp + 4*u);
                const int c = cb + 4*u;
                KS[r*65 + c+0] = t.x;
                KS[r*65 + c+1] = t.y;
                KS[r*65 + c+2] = t.z;
                KS[r*65 + c+3] = t.w;
                const float4 tv = *(const float4*)(vp + 4*u);
                *(float4*)(&VS[r*68 + c]) = tv;
            }
        }
        __syncthreads();

        float sc[4][4];
#pragma unroll
        for (int i = 0; i < 4; i++)
#pragma unroll
            for (int j = 0; j < 4; j++) sc[i][j] = 0.f;

#pragma unroll 8
        for (int d = 0; d < 64; d++) {
            float qv[4];
            *(float4*)qv = *(const float4*)(QT + d*68 + tm0);
            float kv[4];
            kv[0] = KS[(tn0+0)*65 + d];
            kv[1] = KS[(tn0+1)*65 + d];
            kv[2] = KS[(tn0+2)*65 + d];
            kv[3] = KS[(tn0+3)*65 + d];
#pragma unroll
            for (int i = 0; i < 4; i++)
#pragma unroll
                for (int j = 0; j < 4; j++)
                    sc[i][j] += qv[i]*kv[j];
        }

        if (kt < 16) {
#pragma unroll
            for (int i = 0; i < 4; i++) {
                const float4 w4 = *(const float4*)(AW +
                    ((size_t)b*NQ + q0 + tm0 + i)*NKK + kt*64 + tn0);
                sc[i][0] = sc[i][0]*0.125f*w4.x;
                sc[i][1] = sc[i][1]*0.125f*w4.y;
                sc[i][2] = sc[i][2]*0.125f*w4.z;
                sc[i][3] = sc[i][3]*0.125f*w4.w;
            }
        } else {
#pragma unroll
            for (int i = 0; i < 4; i++)
#pragma unroll
                for (int j = 0; j < 4; j++)
                    sc[i][j] = (tn0 + j < NM) ? sc[i][j]*0.125f : -1e30f;
        }

#pragma unroll
        for (int i = 0; i < 4; i++) {
            float rm = fmaxf(fmaxf(sc[i][0], sc[i][1]), fmaxf(sc[i][2], sc[i][3]));
            rm = fmaxf(rm, __shfl_xor_sync(0xffffffffu, rm, 1));
            rm = fmaxf(rm, __shfl_xor_sync(0xffffffffu, rm, 2));
            rm = fmaxf(rm, __shfl_xor_sync(0xffffffffu, rm, 4));
            rm = fmaxf(rm, __shfl_xor_sync(0xffffffffu, rm, 8));
            const float mnew = fmaxf(mrow[i], rm);
            const float corr = __expf(mrow[i] - mnew);
            mrow[i] = mnew;
            const float p0 = __expf(sc[i][0] - mnew);
            const float p1 = __expf(sc[i][1] - mnew);
            const float p2 = __expf(sc[i][2] - mnew);
            const float p3 = __expf(sc[i][3] - mnew);
            float ps = p0 + p1 + p2 + p3;
            ps += __shfl_xor_sync(0xffffffffu, ps, 1);
            ps += __shfl_xor_sync(0xffffffffu, ps, 2);
            ps += __shfl_xor_sync(0xffffffffu, ps, 4);
            ps += __shfl_xor_sync(0xffffffffu, ps, 8);
            lrow[i] = lrow[i]*corr + ps;
            o[i][0] *= corr; o[i][1] *= corr; o[i][2] *= corr; o[i][3] *= corr;
            *(float4*)(&PS[(tm0+i)*68 + tn0]) = make_float4(p0, p1, p2, p3);
        }
        __syncthreads();

#pragma unroll 8
        for (int k = 0; k < 64; k++) {
            float vv[4];
            *(float4*)vv = *(const float4*)(&VS[k*68 + tn0]);
            const float p0 = PS[(tm0+0)*68 + k];
            const float p1 = PS[(tm0+1)*68 + k];
            const float p2 = PS[(tm0+2)*68 + k];
            const float p3 = PS[(tm0+3)*68 + k];
#pragma unroll
            for (int j = 0; j < 4; j++) {
                o[0][j] += p0*vv[j];
                o[1][j] += p1*vv[j];
                o[2][j] += p2*vv[j];
                o[3][j] += p3*vv[j];
            }
        }
    }

#pragma unroll
    for (int i = 0; i < 4; i++) {
        const float inv = 1.0f / lrow[i];
        float4 r;
        r.x = o[i][0]*inv; r.y = o[i][1]*inv; r.z = o[i][2]*inv; r.w = o[i][3]*inv;
        *(float4*)(&g_O[((size_t)b*NQ + q0 + tm0 + i)*DM + h*DKH + tn0]) = r;
    }
}

// ============================================================
// LayerNorm: warp per row (512 elems), eps=1e-3
// ============================================================
__global__ void __launch_bounds__(256) ln_kernel(const float* __restrict__ gamma,
                                                 const float* __restrict__ beta,
                                                 float* __restrict__ out)
{
    const int row = blockIdx.x*8 + (threadIdx.x >> 5);
    const int lane = threadIdx.x & 31;
    const float* xr = g_X + (size_t)row*DM;
    float v[16];
    float s = 0.f, s2 = 0.f;
#pragma unroll
    for (int u = 0; u < 4; u++) {
        const float4 t = *(const float4*)(xr + lane*4 + u*128);
        v[4*u+0] = t.x; v[4*u+1] = t.y; v[4*u+2] = t.z; v[4*u+3] = t.w;
        s  += t.x + t.y + t.z + t.w;
        s2 += t.x*t.x + t.y*t.y + t.z*t.z + t.w*t.w;
    }
#pragma unroll
    for (int off = 16; off > 0; off >>= 1) {
        s  += __shfl_xor_sync(0xffffffffu, s,  off);
        s2 += __shfl_xor_sync(0xffffffffu, s2, off);
    }
    const float mu  = s * (1.f/512.f);
    const float var = s2 * (1.f/512.f) - mu*mu;
    const float rs  = rsqrtf(var + 1e-3f);
    float* orow = out + (size_t)row*DM;
#pragma unroll
    for (int u = 0; u < 4; u++) {
        const int d = lane*4 + u*128;
        const float4 g  = *(const float4*)(gamma + d);
        const float4 bt = *(const float4*)(beta + d);
        float4 r;
        r.x = g.x*(v[4*u+0]-mu)*rs + bt.x;
        r.y = g.y*(v[4*u+1]-mu)*rs + bt.y;
        r.z = g.z*(v[4*u+2]-mu)*rs + bt.z;
        r.w = g.w*(v[4*u+3]-mu)*rs + bt.w;
        *(float4*)(orow + d) = r;
    }
}

// ============================================================
extern "C" void kernel_launch(void* const* d_in, const int* in_sizes, int n_in,
                              void* d_out, int out_size)
{
    (void)in_sizes; (void)n_in; (void)out_size;
    const float* queries = (const float*)d_in[0];
    const float* keys    = (const float*)d_in[1];
    const float* values  = (const float*)d_in[2];
    const float* aw      = (const float*)d_in[3];
    const float* bq = (const float*)d_in[5];
    const float* bk = (const float*)d_in[7];
    const float* bv = (const float*)d_in[9];
    const float* bo = (const float*)d_in[11];
    const float* memK = (const float*)d_in[12];
    const float* memV = (const float*)d_in[13];
    const float* gamma = (const float*)d_in[14];
    const float* beta  = (const float*)d_in[15];
    float* out = (float*)d_out;

    cudaFuncSetAttribute(attn_kernel,
                         cudaFuncAttributeMaxDynamicSharedMemorySize,
                         ATT_SMEM_BYTES);

    const dim3 gg(4, 128);     // 128-col N tiles x 128-row M tiles
    wt_kernel<<<dim3(16, 16, 4), dim3(32, 8)>>>(
        (const float*)d_in[4], (const float*)d_in[6],
        (const float*)d_in[8], (const float*)d_in[10]);
    memfill_kernel<<<128, 256>>>(memK, memV);
    gemm_mma<0><<<gg, 256>>>(queries, 0, bq, nullptr);
    gemm_mma<1><<<gg, 256>>>(keys,    1, bk, nullptr);
    gemm_mma<2><<<gg, 256>>>(values,  2, bv, nullptr);
    attn_kernel<<<dim3(16, 128), 256, ATT_SMEM_BYTES>>>(aw);
    gemm_mma<3><<<gg, 256>>>(nullptr, 3, bo, queries);
    ln_kernel<<<ROWS/8, 256>>>(gamma, beta, out);
}

// round 4
// speedup vs baseline: 1.9455x; 1.4059x over previous
#include <cuda_runtime.h>
#include <cstdint>
#include <math.h>

// Problem constants
#define NB 16
#define NQ 1024
#define NKK 1024
#define DM 512
#define NH 8
#define DKH 64
#define NM 40
#define NKP 1088          // padded key length: 17 * 64
#define ROWS (NB*NQ)      // 16384

// -------- scratch (static device memory: allowed) --------
__device__ float g_Q[(size_t)NB*NH*NQ*DKH];     // [bh][1024][64]
__device__ float g_K[(size_t)NB*NH*NKP*DKH];    // [bh][1088][64]
__device__ float g_V[(size_t)NB*NH*NKP*DKH];    // [bh][1088][64]
__device__ float g_O[(size_t)ROWS*DM];          // attention out, [row][512]
__device__ float g_X[(size_t)ROWS*DM];          // proj + residual, [row][512]
__device__ float g_Wt[4][(size_t)DM*DM];        // transposed weights [n][k]

// ============================================================
// tf32 helpers (base-ISA only: mma.sync)
// ============================================================
__device__ __forceinline__ uint32_t f2tf32(float f) {
    uint32_t r;
    asm("cvt.rna.tf32.f32 %0, %1;" : "=r"(r) : "f"(f));
    return r;
}

__device__ __forceinline__ void mma_tf32(float* c, const uint32_t* a, const uint32_t* b) {
    asm volatile(
        "mma.sync.aligned.m16n8k8.row.col.f32.tf32.tf32.f32 "
        "{%0,%1,%2,%3}, {%4,%5,%6,%7}, {%8,%9}, {%0,%1,%2,%3};"
        : "+f"(c[0]), "+f"(c[1]), "+f"(c[2]), "+f"(c[3])
        : "r"(a[0]), "r"(a[1]), "r"(a[2]), "r"(a[3]), "r"(b[0]), "r"(b[1]));
}

// ============================================================
// Weight transpose: g_Wt[z][n][k] = W_z[k][n]  (512x512 each)
// ============================================================
__global__ void wt_kernel(const float* __restrict__ Wq, const float* __restrict__ Wk,
                          const float* __restrict__ Wv, const float* __restrict__ Wo)
{
    __shared__ float t[32][33];
    const int z = blockIdx.z;
    const float* W = (z == 0) ? Wq : (z == 1) ? Wk : (z == 2) ? Wv : Wo;
    const int tx = threadIdx.x, ty = threadIdx.y;
    const int nx = blockIdx.x*32 + tx;
    const int ky = blockIdx.y*32 + ty;
#pragma unroll
    for (int i = 0; i < 32; i += 8)
        t[ty + i][tx] = W[(size_t)(ky + i)*DM + nx];
    __syncthreads();
    const int ok = blockIdx.y*32 + tx;
    const int on = blockIdx.x*32 + ty;
#pragma unroll
    for (int i = 0; i < 32; i += 8)
        g_Wt[z][(size_t)(on + i)*DM + ok] = t[tx][ty + i];
}

// ============================================================
// Memory-slot fill: rows 1024..1087 of g_K/g_V (scaled mem, zero pad)
// ============================================================
__global__ void memfill_kernel(const float* __restrict__ memK,
                               const float* __restrict__ memV)
{
    const int bh = blockIdx.x;          // 0..127
    const int h = bh & 7;
    const float sk = 8.0f;              // sqrt(64)
    const float sv = 6.3245553203367587f; // sqrt(40)
    for (int idx = threadIdx.x; idx < 64*64; idx += blockDim.x) {
        const int m = idx >> 6;
        const int d = idx & 63;
        float kv = 0.f, vv = 0.f;
        if (m < NM) {
            kv = sk * memK[m*DM + h*DKH + d];
            vv = sv * memV[m*DM + h*DKH + d];
        }
        const size_t o = ((size_t)bh*NKP + 1024 + m)*DKH + d;
        g_K[o] = kv;
        g_V[o] = vv;
    }
}

// ============================================================
// mma.sync tf32 GEMM: C[16384,512] = A @ Wt^T + bias
// Block 128x128, BK=32, 256 threads (8 warps, warp tile 64x32).
// ============================================================
#define KPAD 36

template<int MODE>
__global__ void __launch_bounds__(256) gemm_mma(const float* __restrict__ A,
                                                int widx,
                                                const float* __restrict__ bias,
                                                const float* __restrict__ resid)
{
    __shared__ float As[128*KPAD];
    __shared__ float Bs[128*KPAD];

    const int tid = threadIdx.x;
    const int lane = tid & 31, wid = tid >> 5;
    const int wm = (wid & 1) << 6;
    const int wn = (wid >> 1) << 5;
    const int gr = lane >> 2, tc = lane & 3;
    const int m0 = blockIdx.y << 7, n0 = blockIdx.x << 7;

    const float* Ap = (MODE == 3) ? (const float*)g_O : A;
    const float* Wt = g_Wt[widx];

    const int lrow = tid >> 1;
    const int lcol = (tid & 1) << 4;

    const float* Ag = Ap + (size_t)(m0 + lrow)*DM + lcol;
    const float* Bg = Wt + (size_t)(n0 + lrow)*DM + lcol;
    float* as_st = &As[lrow*KPAD + lcol];
    float* bs_st = &Bs[lrow*KPAD + lcol];

    float acc[4][4][4];
#pragma unroll
    for (int i = 0; i < 4; i++)
#pragma unroll
        for (int j = 0; j < 4; j++)
#pragma unroll
            for (int r = 0; r < 4; r++) acc[i][j][r] = 0.f;

    const uint32_t* Asu = (const uint32_t*)As;
    const uint32_t* Bsu = (const uint32_t*)Bs;

    for (int kb = 0; kb < DM; kb += 32) {
        float4 av[4], bv[4];
#pragma unroll
        for (int u = 0; u < 4; u++) {
            av[u] = *(const float4*)(Ag + kb + 4*u);
            bv[u] = *(const float4*)(Bg + kb + 4*u);
        }
        __syncthreads();
#pragma unroll
        for (int u = 0; u < 4; u++) {
            uint32_t* d = (uint32_t*)(as_st + 4*u);
            d[0] = f2tf32(av[u].x); d[1] = f2tf32(av[u].y);
            d[2] = f2tf32(av[u].z); d[3] = f2tf32(av[u].w);
            uint32_t* e = (uint32_t*)(bs_st + 4*u);
            e[0] = f2tf32(bv[u].x); e[1] = f2tf32(bv[u].y);
            e[2] = f2tf32(bv[u].z); e[3] = f2tf32(bv[u].w);
        }
        __syncthreads();

#pragma unroll
        for (int ks = 0; ks < 32; ks += 8) {
            uint32_t a[4][4], b[4][2];
#pragma unroll
            for (int i = 0; i < 4; i++) {
                const int r0 = (wm + i*16 + gr)*KPAD + ks + tc;
                a[i][0] = Asu[r0];
                a[i][1] = Asu[r0 + 8*KPAD];
                a[i][2] = Asu[r0 + 4];
                a[i][3] = Asu[r0 + 8*KPAD + 4];
            }
#pragma unroll
            for (int j = 0; j < 4; j++) {
                const int r0 = (wn + j*8 + gr)*KPAD + ks + tc;
                b[j][0] = Bsu[r0];
                b[j][1] = Bsu[r0 + 4];
            }
#pragma unroll
            for (int i = 0; i < 4; i++)
#pragma unroll
                for (int j = 0; j < 4; j++)
                    mma_tf32(acc[i][j], a[i], b[j]);
        }
    }

#pragma unroll
    for (int i = 0; i < 4; i++) {
        const int mA = m0 + wm + i*16 + gr;
        const int mB = mA + 8;
#pragma unroll
        for (int j = 0; j < 4; j++) {
            const int n = n0 + wn + j*8 + 2*tc;
            const float b0 = bias[n], b1 = bias[n+1];
            float2 vA = make_float2(acc[i][j][0] + b0, acc[i][j][1] + b1);
            float2 vB = make_float2(acc[i][j][2] + b0, acc[i][j][3] + b1);
            if (MODE == 3) {
                const float2 rA = *(const float2*)(resid + (size_t)mA*DM + n);
                const float2 rB = *(const float2*)(resid + (size_t)mB*DM + n);
                vA.x += rA.x; vA.y += rA.y;
                vB.x += rB.x; vB.y += rB.y;
                *(float2*)(&g_X[(size_t)mA*DM + n]) = vA;
                *(float2*)(&g_X[(size_t)mB*DM + n]) = vB;
            } else {
                const int h = n >> 6, d = n & 63;
                const int bbA = mA >> 10, nnA = mA & 1023;
                const int bbB = mB >> 10, nnB = mB & 1023;
                if (MODE == 0) {
                    *(float2*)(&g_Q[(((size_t)bbA*NH + h)*NQ + nnA)*DKH + d]) = vA;
                    *(float2*)(&g_Q[(((size_t)bbB*NH + h)*NQ + nnB)*DKH + d]) = vB;
                } else if (MODE == 1) {
                    *(float2*)(&g_K[(((size_t)bbA*NH + h)*NKP + nnA)*DKH + d]) = vA;
                    *(float2*)(&g_K[(((size_t)bbB*NH + h)*NKP + nnB)*DKH + d]) = vB;
                } else {
                    *(float2*)(&g_V[(((size_t)bbA*NH + h)*NKP + nnA)*DKH + d]) = vA;
                    *(float2*)(&g_V[(((size_t)bbB*NH + h)*NKP + nnB)*DKH + d]) = vB;
                }
            }
        }
    }
}

// ============================================================
// Tensor-core flash attention (mma.sync tf32).
// Block = one (b,h) x 64 queries, 4 warps (16 q-rows each).
// S = (0.125*Q) @ K^T per 64-key tile; online softmax in C-regs;
// P round-trips SMEM (warp-private rows, __syncwarp only);
// O accumulates in mma C-regs with per-row rescale.
// ============================================================
#define ASTRIDE 68
#define ATT2_SMEM (3*64*ASTRIDE*4)

__global__ void __launch_bounds__(128) attn_mma_kernel(const float* __restrict__ AW)
{
    extern __shared__ uint32_t dsm[];
    uint32_t* Ks = dsm;                  // [k][d] tf32 bits
    uint32_t* Vs = Ks + 64*ASTRIDE;      // [k][dv] tf32 bits
    uint32_t* Ps = Vs + 64*ASTRIDE;      // Q staging, then P [q][k] tf32 bits

    const int tid = threadIdx.x, lane = tid & 31, wid = tid >> 5;
    const int bh = blockIdx.y, b = bh >> 3, h = bh & 7;
    const int q0 = blockIdx.x << 6;
    const int gr = lane >> 2, tc = lane & 3;
    const int qw = wid << 4;

    // ---- stage Q (pre-scaled by 1/sqrt(dk)=0.125, tf32) ----
    {
        const int r = tid >> 1, c0 = (tid & 1) << 5;
        const float* qp = g_Q + ((size_t)bh*NQ + q0 + r)*DKH + c0;
#pragma unroll
        for (int u = 0; u < 8; u++) {
            const float4 t = *(const float4*)(qp + 4*u);
            uint4 w;
            w.x = f2tf32(0.125f*t.x); w.y = f2tf32(0.125f*t.y);
            w.z = f2tf32(0.125f*t.z); w.w = f2tf32(0.125f*t.w);
            *(uint4*)(&Ps[r*ASTRIDE + c0 + 4*u]) = w;
        }
    }
    __syncthreads();

    uint32_t qf[8][4];
#pragma unroll
    for (int ks = 0; ks < 8; ks++) {
        const int r0 = (qw + gr)*ASTRIDE + ks*8 + tc;
        qf[ks][0] = Ps[r0];
        qf[ks][1] = Ps[r0 + 8*ASTRIDE];
        qf[ks][2] = Ps[r0 + 4];
        qf[ks][3] = Ps[r0 + 8*ASTRIDE + 4];
    }

    float o[8][4];
#pragma unroll
    for (int j = 0; j < 8; j++)
#pragma unroll
        for (int r = 0; r < 4; r++) o[j][r] = 0.f;
    float m0 = -1e30f, m1 = -1e30f, l0 = 0.f, l1 = 0.f;

    for (int kt = 0; kt < 17; kt++) {
        __syncthreads();   // protects Ks/Vs (all) and Ps (Q-frag reads in iter 0)
        {
            const int r = tid >> 1, c0 = (tid & 1) << 5;
            const float* kp = g_K + ((size_t)bh*NKP + kt*64 + r)*DKH + c0;
            const float* vp = g_V + ((size_t)bh*NKP + kt*64 + r)*DKH + c0;
#pragma unroll
            for (int u = 0; u < 8; u++) {
                const float4 t = *(const float4*)(kp + 4*u);
                uint4 w;
                w.x = f2tf32(t.x); w.y = f2tf32(t.y);
                w.z = f2tf32(t.z); w.w = f2tf32(t.w);
                *(uint4*)(&Ks[r*ASTRIDE + c0 + 4*u]) = w;
                const float4 v = *(const float4*)(vp + 4*u);
                uint4 x;
                x.x = f2tf32(v.x); x.y = f2tf32(v.y);
                x.z = f2tf32(v.z); x.w = f2tf32(v.w);
                *(uint4*)(&Vs[r*ASTRIDE + c0 + 4*u]) = x;
            }
        }
        __syncthreads();

        // ---- S = Qs @ K^T ----
        float sc[8][4];
#pragma unroll
        for (int j = 0; j < 8; j++) {
            sc[j][0] = sc[j][1] = sc[j][2] = sc[j][3] = 0.f;
#pragma unroll
            for (int ks = 0; ks < 8; ks++) {
                uint32_t bb[2];
                const int r0 = (j*8 + gr)*ASTRIDE + ks*8 + tc;
                bb[0] = Ks[r0];
                bb[1] = Ks[r0 + 4];
                mma_tf32(sc[j], qf[ks], bb);
            }
        }

        // ---- attention_weights / memory mask ----
        if (kt < 16) {
            const float* aw0 = AW + ((size_t)b*NQ + q0 + qw + gr)*NKK + kt*64 + 2*tc;
            const float* aw1 = aw0 + 8*(size_t)NKK;
#pragma unroll
            for (int j = 0; j < 8; j++) {
                const float2 w0 = *(const float2*)(aw0 + j*8);
                const float2 w1 = *(const float2*)(aw1 + j*8);
                sc[j][0] *= w0.x; sc[j][1] *= w0.y;
                sc[j][2] *= w1.x; sc[j][3] *= w1.y;
            }
        } else {
#pragma unroll
            for (int j = 0; j < 8; j++) {
                const int c = j*8 + 2*tc;
                if (c >= NM)     { sc[j][0] = -1e30f; sc[j][2] = -1e30f; }
                if (c + 1 >= NM) { sc[j][1] = -1e30f; sc[j][3] = -1e30f; }
            }
        }

        // ---- online softmax ----
        float rm0 = -1e30f, rm1 = -1e30f;
#pragma unroll
        for (int j = 0; j < 8; j++) {
            rm0 = fmaxf(rm0, fmaxf(sc[j][0], sc[j][1]));
            rm1 = fmaxf(rm1, fmaxf(sc[j][2], sc[j][3]));
        }
        rm0 = fmaxf(rm0, __shfl_xor_sync(0xffffffffu, rm0, 1));
        rm0 = fmaxf(rm0, __shfl_xor_sync(0xffffffffu, rm0, 2));
        rm1 = fmaxf(rm1, __shfl_xor_sync(0xffffffffu, rm1, 1));
        rm1 = fmaxf(rm1, __shfl_xor_sync(0xffffffffu, rm1, 2));
        const float mn0 = fmaxf(m0, rm0), mn1 = fmaxf(m1, rm1);
        const float c0 = __expf(m0 - mn0), c1 = __expf(m1 - mn1);
        m0 = mn0; m1 = mn1;

        float s0 = 0.f, s1 = 0.f;
        uint32_t* pr0 = &Ps[(qw + gr)*ASTRIDE + 2*tc];
        uint32_t* pr1 = pr0 + 8*ASTRIDE;
#pragma unroll
        for (int j = 0; j < 8; j++) {
            const float p00 = __expf(sc[j][0] - mn0);
            const float p01 = __expf(sc[j][1] - mn0);
            const float p10 = __expf(sc[j][2] - mn1);
            const float p11 = __expf(sc[j][3] - mn1);
            s0 += p00 + p01;
            s1 += p10 + p11;
            uint2 u0; u0.x = f2tf32(p00); u0.y = f2tf32(p01);
            uint2 u1; u1.x = f2tf32(p10); u1.y = f2tf32(p11);
            *(uint2*)(pr0 + j*8) = u0;
            *(uint2*)(pr1 + j*8) = u1;
        }
        s0 += __shfl_xor_sync(0xffffffffu, s0, 1);
        s0 += __shfl_xor_sync(0xffffffffu, s0, 2);
        s1 += __shfl_xor_sync(0xffffffffu, s1, 1);
        s1 += __shfl_xor_sync(0xffffffffu, s1, 2);
        l0 = l0*c0 + s0;
        l1 = l1*c1 + s1;
#pragma unroll
        for (int j = 0; j < 8; j++) {
            o[j][0] *= c0; o[j][1] *= c0;
            o[j][2] *= c1; o[j][3] *= c1;
        }
        __syncwarp();   // P rows are warp-private: make stores visible in-warp

        // ---- O += P @ V ----
#pragma unroll
        for (int ks = 0; ks < 8; ks++) {
            uint32_t a[4];
            const int r0 = (qw + gr)*ASTRIDE + ks*8 + tc;
            a[0] = Ps[r0];
            a[1] = Ps[r0 + 8*ASTRIDE];
            a[2] = Ps[r0 + 4];
            a[3] = Ps[r0 + 8*ASTRIDE + 4];
#pragma unroll
            for (int j = 0; j < 8; j++) {
                uint32_t bb[2];
                bb[0] = Vs[(ks*8 + tc)*ASTRIDE + j*8 + gr];
                bb[1] = Vs[(ks*8 + tc + 4)*ASTRIDE + j*8 + gr];
                mma_tf32(o[j], a, bb);
            }
        }
    }

    // ---- normalize + write ----
    const float inv0 = 1.0f / l0, inv1 = 1.0f / l1;
    float* op0 = g_O + ((size_t)b*NQ + q0 + qw + gr)*DM + h*DKH + 2*tc;
    float* op1 = op0 + 8*(size_t)DM;
#pragma unroll
    for (int j = 0; j < 8; j++) {
        *(float2*)(op0 + j*8) = make_float2(o[j][0]*inv0, o[j][1]*inv0);
        *(float2*)(op1 + j*8) = make_float2(o[j][2]*inv1, o[j][3]*inv1);
    }
}

// ============================================================
// LayerNorm: warp per row (512 elems), eps=1e-3
// ============================================================
__global__ void __launch_bounds__(256) ln_kernel(const float* __restrict__ gamma,
                                                 const float* __restrict__ beta,
                                                 float* __restrict__ out)
{
    const int row = blockIdx.x*8 + (threadIdx.x >> 5);
    const int lane = threadIdx.x & 31;
    const float* xr = g_X + (size_t)row*DM;
    float v[16];
    float s = 0.f, s2 = 0.f;
#pragma unroll
    for (int u = 0; u < 4; u++) {
        const float4 t = *(const float4*)(xr + lane*4 + u*128);
        v[4*u+0] = t.x; v[4*u+1] = t.y; v[4*u+2] = t.z; v[4*u+3] = t.w;
        s  += t.x + t.y + t.z + t.w;
        s2 += t.x*t.x + t.y*t.y + t.z*t.z + t.w*t.w;
    }
#pragma unroll
    for (int off = 16; off > 0; off >>= 1) {
        s  += __shfl_xor_sync(0xffffffffu, s,  off);
        s2 += __shfl_xor_sync(0xffffffffu, s2, off);
    }
    const float mu  = s * (1.f/512.f);
    const float var = s2 * (1.f/512.f) - mu*mu;
    const float rs  = rsqrtf(var + 1e-3f);
    float* orow = out + (size_t)row*DM;
#pragma unroll
    for (int u = 0; u < 4; u++) {
        const int d = lane*4 + u*128;
        const float4 g  = *(const float4*)(gamma + d);
        const float4 bt = *(const float4*)(beta + d);
        float4 r;
        r.x = g.x*(v[4*u+0]-mu)*rs + bt.x;
        r.y = g.y*(v[4*u+1]-mu)*rs + bt.y;
        r.z = g.z*(v[4*u+2]-mu)*rs + bt.z;
        r.w = g.w*(v[4*u+3]-mu)*rs + bt.w;
        *(float4*)(orow + d) = r;
    }
}

// ============================================================
extern "C" void kernel_launch(void* const* d_in, const int* in_sizes, int n_in,
                              void* d_out, int out_size)
{
    (void)in_sizes; (void)n_in; (void)out_size;
    const float* queries = (const float*)d_in[0];
    const float* keys    = (const float*)d_in[1];
    const float* values  = (const float*)d_in[2];
    const float* aw      = (const float*)d_in[3];
    const float* bq = (const float*)d_in[5];
    const float* bk = (const float*)d_in[7];
    const float* bv = (const float*)d_in[9];
    const float* bo = (const float*)d_in[11];
    const float* memK = (const float*)d_in[12];
    const float* memV = (const float*)d_in[13];
    const float* gamma = (const float*)d_in[14];
    const float* beta  = (const float*)d_in[15];
    float* out = (float*)d_out;

    cudaFuncSetAttribute(attn_mma_kernel,
                         cudaFuncAttributeMaxDynamicSharedMemorySize,
                         ATT2_SMEM);

    const dim3 gg(4, 128);
    wt_kernel<<<dim3(16, 16, 4), dim3(32, 8)>>>(
        (const float*)d_in[4], (const float*)d_in[6],
        (const float*)d_in[8], (const float*)d_in[10]);
    memfill_kernel<<<128, 256>>>(memK, memV);
    gemm_mma<0><<<gg, 256>>>(queries, 0, bq, nullptr);
    gemm_mma<1><<<gg, 256>>>(keys,    1, bk, nullptr);
    gemm_mma<2><<<gg, 256>>>(values,  2, bv, nullptr);
    attn_mma_kernel<<<dim3(16, 128), 128, ATT2_SMEM>>>(aw);
    gemm_mma<3><<<gg, 256>>>(nullptr, 3, bo, queries);
    ln_kernel<<<ROWS/8, 256>>>(gamma, beta, out);
}